// round 16
// baseline (speedup 1.0000x reference)
#include <cuda_runtime.h>
#include <math.h>

#define YPB 128                      // years per block -> 64 blocks, 1/SM, all co-resident
#define PI_F 3.14159265358979323846f

__device__ __forceinline__ float fast_lg2(float x) {
    float r; asm("lg2.approx.f32 %0, %1;" : "=f"(r) : "f"(x)); return r;
}
__device__ __forceinline__ float fast_ex2(float x) {
    float r; asm("ex2.approx.f32 %0, %1;" : "=f"(r) : "f"(x)); return r;
}
__device__ __forceinline__ float fast_pow(float x, float e) {
    return fast_ex2(e * fast_lg2(x));     // x=0 -> -inf -> 0
}
// deg-9 odd asin, |x| <= ~0.45 (err < 4e-6)
__device__ __forceinline__ float asin_poly(float x) {
    float x2 = x * x;
    float p = fmaf(x2, 0.030381944f, 0.044642857f);
    p = fmaf(x2, p, 0.075f);
    p = fmaf(x2, p, 0.16666667f);
    return fmaf(x * x2, p, x);
}
__device__ __forceinline__ float fast_acos(float x) {
    return (fabsf(x) <= 0.45f) ? (PI_F * 0.5f - asin_poly(x)) : acosf(x);
}

// ---------------- device state (no allocation) ----------------
__device__ float        g_sum   = 0.0f;
__device__ float        g_sumsq = 0.0f;
__device__ unsigned int g_ticket = 0;
__device__ float        g_gen   = 0.0f;                       // replay generation
__device__ float4       g_stats = {0.0f, 0.0f, 0.0f, 0.0f};   // {mean, inv, gen, pad}

__device__ __constant__ float c_NDAYS[13] = {0,31,28,31,30,31,30,31,31,30,31,30,31};
__device__ __constant__ float c_INVND[12] = {
    1.0f/31.0f, 1.0f/28.0f, 1.0f/31.0f, 1.0f/30.0f, 1.0f/31.0f, 1.0f/30.0f,
    1.0f/31.0f, 1.0f/31.0f, 1.0f/30.0f, 1.0f/31.0f, 1.0f/30.0f, 1.0f/31.0f };
__device__ __constant__ int   c_CDAYS[13] = {0,31,59,90,120,151,181,212,243,273,304,334,365};

// PET for one year: (T[12], P[12]) + sh_L -> A[12], B[12]; optionally gT[12]
__device__ __forceinline__ void pet_year(const float* __restrict__ t, const float* __restrict__ p,
                                         const float* __restrict__ Lsh,
                                         float T1, float invDT,
                                         float* __restrict__ A, float* __restrict__ B,
                                         float* __restrict__ gT, bool wantGT) {
    float I = 0.0f;
    #pragma unroll
    for (int m = 0; m < 12; m++)
        I += fast_pow(fmaxf(t[m] * 0.2f, 0.0f), 1.514f);
    const float a    = ((6.75e-7f * I - 7.71e-5f) * I + 0.0179f) * I + 0.49f;
    const float invI = 1.0f / I;
    #pragma unroll
    for (int m = 0; m < 12; m++) {
        float Tm = t[m];
        float ep = (Tm < 26.5f)
            ? 16.0f * Lsh[m] * fast_pow(fmaxf(10.0f * Tm * invI, 0.0f), a)
            : -415.85f + 32.25f * Tm - 0.43f * Tm * Tm;
        A[m] = 0.907f - ep * 1.31578947e-3f;
        B[m] = p[m] * 1.31578947e-3f;              // B' = p*0.001/0.76 (r-space)
        if (wantGT) gT[m] = fminf(fmaxf((Tm - T1) * invDT, 0.0f), 1.0f);
    }
}

__global__ void __launch_bounds__(YPB, 1)
vsl_fused_kernel(const int* __restrict__ phi_ptr,
                 const float* __restrict__ T, const float* __restrict__ P,
                 const float* __restrict__ pT1, const float* __restrict__ pT2,
                 const float* __restrict__ pM1, const float* __restrict__ pM2,
                 float* __restrict__ out, int nyrs) {
    __shared__ float        sh_L[12];
    __shared__ float        sh_msum[12];
    __shared__ unsigned int sh_mmax;
    __shared__ float        sh_red[8];

    const int tid = threadIdx.x;
    const int y   = blockIdx.x * YPB + tid;     // this thread's real year
    const int yw  = y - 1;                      // warmup year

    // ---- entry: generation stamp + scalars + both years' data (loads in flight) ----
    const float genExp = __ldcg(&g_gen) + 1.0f;
    const float T1 = *pT1, T2 = *pT2, M1 = *pM1, M2 = *pM2;

    const bool vR = (y < nyrs);
    const bool vW = (yw >= 0) && (yw < nyrs);
    float4 r0 = make_float4(0.f,0.f,0.f,0.f), r1 = r0, r2 = r0;   // T real
    float4 q0 = r0, q1 = r0, q2 = r0;                             // P real
    float4 w0 = r0, w1 = r0, w2 = r0;                             // T warm
    float4 v0 = r0, v1 = r0, v2 = r0;                             // P warm
    if (vR) {
        const float4* Tv = reinterpret_cast<const float4*>(T + y * 12);
        const float4* Pv = reinterpret_cast<const float4*>(P + y * 12);
        r0 = Tv[0]; r1 = Tv[1]; r2 = Tv[2];
        q0 = Pv[0]; q1 = Pv[1]; q2 = Pv[2];
    }
    if (vW) {
        const float4* Tv = reinterpret_cast<const float4*>(T + yw * 12);
        const float4* Pv = reinterpret_cast<const float4*>(P + yw * 12);
        w0 = Tv[0]; w1 = Tv[1]; w2 = Tv[2];
        v0 = Pv[0]; v1 = Pv[1]; v2 = Pv[2];
    }

    const float latr  = (float)(*phi_ptr) * (PI_F / 180.0f);
    const float invDT = 1.0f / (T2 - T1);
    const float invDM = 1.0f / (M2 - M1);

    // ---- init month accumulators ----
    if (tid < 12) sh_msum[tid] = 0.0f;
    if (tid == 12) sh_mmax = 0u;
    __syncthreads();

    // ---- stage 1: daily insolation -> month-bucketed sums + max (atomics) ----
    const float tlat = __tanf(latr);
    const float slat = __sinf(latr);
    const float clat = __cosf(latr);
    float lmax = 0.0f;
    #pragma unroll
    for (int k = 0; k < 3; k++) {
        int j = tid + k * YPB;
        if (j < 365) {
            float jday = (float)(j + 1);
            float ssd  = 0.39874907f * __sinf(PI_F * (jday - 80.0f) * (1.0f / 180.0f));
            float csd  = sqrtf(1.0f - ssd * ssd);
            float yv   = fminf(fmaxf(-tlat * ssd * (1.0f / csd), -1.0f), 1.0f);
            float hdl  = fast_acos(yv);
            float shdl = sqrtf(fmaxf(1.0f - yv * yv, 0.0f));
            float dtsi = hdl * slat * ssd + clat * csd * shdl;
            int mo = 0;
            #pragma unroll
            for (int q = 1; q < 12; q++) mo += (j >= c_CDAYS[q]);
            atomicAdd(&sh_msum[mo], dtsi);
            lmax = fmaxf(lmax, dtsi);
        }
    }
    #pragma unroll
    for (int o = 16; o > 0; o >>= 1)
        lmax = fmaxf(lmax, __shfl_xor_sync(0xFFFFFFFF, lmax, o));
    if ((tid & 31) == 0) atomicMax(&sh_mmax, __float_as_uint(lmax));

    // day-length factor L (12 lanes, no shared deps)
    if (tid < 12) {
        float jday_mid = (float)c_CDAYS[tid] + 0.5f * c_NDAYS[tid + 1];
        float m_star = 1.0f - tlat * __tanf(0.40908772f * __cosf(jday_mid * (PI_F / 182.625f)));
        m_star = fminf(fmaxf(m_star, 0.0f), 2.0f);
        float nhrs = 24.0f * fast_acos(1.0f - m_star) * (1.0f / PI_F);
        sh_L[tid] = c_NDAYS[tid + 1] * (1.0f / 30.0f) * (nhrs * (1.0f / 12.0f));
    }
    __syncthreads();     // THE one pre-chain barrier: sh_L + msum/mmax ready

    // ---- stage 2: PET for both years, all in registers ----
    float Aw[12], Bw[12], Ar[12], Br[12], gT[12];
    {
        float tw[12] = { w0.x,w0.y,w0.z,w0.w, w1.x,w1.y,w1.z,w1.w, w2.x,w2.y,w2.z,w2.w };
        float pw_[12] = { v0.x,v0.y,v0.z,v0.w, v1.x,v1.y,v1.z,v1.w, v2.x,v2.y,v2.z,v2.w };
        if (vW) {
            pet_year(tw, pw_, sh_L, T1, invDT, Aw, Bw, gT, false);
        } else {
            #pragma unroll
            for (int m = 0; m < 12; m++) { Aw[m] = 1.0f; Bw[m] = 0.0f; }   // identity (y==0 exact)
        }
    }
    {
        float tr[12] = { r0.x,r0.y,r0.z,r0.w, r1.x,r1.y,r1.z,r1.w, r2.x,r2.y,r2.z,r2.w };
        float pr[12] = { q0.x,q0.y,q0.z,q0.w, q1.x,q1.y,q1.z,q1.w, q2.x,q2.y,q2.z,q2.w };
        if (vR) {
            pet_year(tr, pr, sh_L, T1, invDT, Ar, Br, gT, true);
        } else {
            #pragma unroll
            for (int m = 0; m < 12; m++) { Ar[m] = 1.0f; Br[m] = 0.0f; gT[m] = 0.0f; }
        }
    }

    // ---- stage 3: chain (pure registers + MUFU; no shared, no barriers) ----
    const float PEXP = 4.886f;
    const float RMIN = 0.01f / 0.76f;
    const float c0g  = 0.76f * invDM;
    const float c1g  = -M1 * invDM;
    const float invmax = 1.0f / __uint_as_float(sh_mmax);

    float r = 0.2f / 0.76f;                 // M0 in r units
    #pragma unroll
    for (int m = 0; m < 12; m++) {          // warmup year
        float pw = fast_ex2(PEXP * fast_lg2(r));
        float tt = fmaf(Aw[m], r, Bw[m]);
        r = fminf(fmaxf(fmaf(-Bw[m], pw, tt), RMIN), 1.0f);
    }
    float w = 0.0f;
    #pragma unroll
    for (int m = 0; m < 12; m++) {          // the real 12 months
        float pw = fast_ex2(PEXP * fast_lg2(r));
        float tt = fmaf(Ar[m], r, Br[m]);
        r = fminf(fmaxf(fmaf(-Br[m], pw, tt), RMIN), 1.0f);

        float gM = fminf(fmaxf(fmaf(r, c0g, c1g), 0.0f), 1.0f);
        float gE = sh_msum[m] * invmax * c_INVND[m];   // broadcast LDS, off chain path
        w = fmaf(fminf(gT[m], gM), gE, w);
    }
    if (!vR) w = 0.0f;

    // ---- stage 4: block sums -> atomics; last arrival publishes {mean,inv,gen} ----
    {
        const int lane = tid & 31;
        const int wid  = tid >> 5;
        float s1 = w, s2 = w * w;
        #pragma unroll
        for (int o = 16; o > 0; o >>= 1) {
            s1 += __shfl_xor_sync(0xFFFFFFFF, s1, o);
            s2 += __shfl_xor_sync(0xFFFFFFFF, s2, o);
        }
        if (lane == 0) { sh_red[wid] = s1; sh_red[4 + wid] = s2; }
        __syncthreads();
        if (tid == 0) {
            float b1 = sh_red[0] + sh_red[1] + sh_red[2] + sh_red[3];
            float b2 = sh_red[4] + sh_red[5] + sh_red[6] + sh_red[7];
            atomicAdd(&g_sum, b1);
            atomicAdd(&g_sumsq, b2);
            __threadfence();
            unsigned int old = atomicAdd(&g_ticket, 1u);
            if (old == gridDim.x - 1u) {
                // every block fenced before its ticket add -> sums complete & visible
                const float n    = (float)nyrs;
                const float sum  = __ldcg(&g_sum);
                const float ssq  = __ldcg(&g_sumsq);
                const float mean = sum / n;
                const float inv  = rsqrtf((ssq - n * mean * mean) / (n - 1.0f));
                g_sum = 0.0f;                 // reset for next replay
                g_sumsq = 0.0f;
                g_ticket = 0;
                g_gen = genExp;
                asm volatile("st.global.cg.v4.f32 [%0], {%1, %2, %3, %4};"
                             :: "l"(&g_stats), "f"(mean), "f"(inv), "f"(genExp), "f"(0.0f)
                             : "memory");
            }
        }
    }

    // ---- stage 5: per-warp poll of the stats line, broadcast, store, exit ----
    {
        const int lane = tid & 31;
        float mean = 0.0f, inv = 0.0f;
        if (lane == 0) {
            float x0, x1, x2, x3;
            for (;;) {
                asm volatile("ld.global.cg.v4.f32 {%0, %1, %2, %3}, [%4];"
                             : "=f"(x0), "=f"(x1), "=f"(x2), "=f"(x3) : "l"(&g_stats));
                if (x2 == genExp) break;
                __nanosleep(20);
            }
            mean = x0; inv = x1;
        }
        mean = __shfl_sync(0xFFFFFFFF, mean, 0);
        inv  = __shfl_sync(0xFFFFFFFF, inv, 0);
        if (vR) out[y] = (w - mean) * inv;
    }
}

// ---------------- launch ----------------
extern "C" void kernel_launch(void* const* d_in, const int* in_sizes, int n_in,
                              void* d_out, int out_size) {
    const int*   phi = (const int*)d_in[2];
    const float* T   = (const float*)d_in[3];
    const float* P   = (const float*)d_in[4];
    const float* T1  = (const float*)d_in[5];
    const float* T2  = (const float*)d_in[6];
    const float* M1  = (const float*)d_in[7];
    const float* M2  = (const float*)d_in[8];
    float* out = (float*)d_out;

    const int nyrs = in_sizes[3] / 12;
    const int nblk = (nyrs + YPB - 1) / YPB;   // 64 <= 148 SMs: all co-resident

    vsl_fused_kernel<<<nblk, YPB>>>(phi, T, P, T1, T2, M1, M2, out, nyrs);
}

// round 17
// speedup vs baseline: 1.3208x; 1.3208x over previous
#include <cuda_runtime.h>
#include <math.h>

#define YPB 128                      // years per block -> 64 blocks, 1/SM, all co-resident
#define W_YEARS 1
#define SLOTS (YPB + W_YEARS)        // 129 year-slots incl. halo
#define PI_F 3.14159265358979323846f

__device__ __forceinline__ float fast_lg2(float x) {
    float r; asm("lg2.approx.f32 %0, %1;" : "=f"(r) : "f"(x)); return r;
}
__device__ __forceinline__ float fast_ex2(float x) {
    float r; asm("ex2.approx.f32 %0, %1;" : "=f"(r) : "f"(x)); return r;
}
__device__ __forceinline__ float fast_pow(float x, float e) {
    return fast_ex2(e * fast_lg2(x));     // x=0 -> -inf -> 0
}
// deg-9 odd asin, |x| <= ~0.45 (err < 4e-6)
__device__ __forceinline__ float asin_poly(float x) {
    float x2 = x * x;
    float p = fmaf(x2, 0.030381944f, 0.044642857f);
    p = fmaf(x2, p, 0.075f);
    p = fmaf(x2, p, 0.16666667f);
    return fmaf(x * x2, p, x);
}
__device__ __forceinline__ float fast_acos(float x) {
    return (fabsf(x) <= 0.45f) ? (PI_F * 0.5f - asin_poly(x)) : acosf(x);
}

// ---------------- device state (no allocation) ----------------
__device__ float        g_sum   = 0.0f;
__device__ float        g_sumsq = 0.0f;
__device__ unsigned int g_ticket = 0;
__device__ float        g_gen   = 0.0f;                       // replay generation
__device__ float4       g_stats = {0.0f, 0.0f, 0.0f, 0.0f};   // {mean, inv, gen, pad}

__device__ __constant__ float c_NDAYS[13] = {0,31,28,31,30,31,30,31,31,30,31,30,31};
__device__ __constant__ int   c_CDAYS[13] = {0,31,59,90,120,151,181,212,243,273,304,334,365};

__global__ void __launch_bounds__(YPB, 1)
vsl_fused_kernel(const int* __restrict__ phi_ptr,
                 const float* __restrict__ T, const float* __restrict__ P,
                 const float* __restrict__ pT1, const float* __restrict__ pT2,
                 const float* __restrict__ pM1, const float* __restrict__ pM2,
                 float* __restrict__ out, int nyrs) {
    __shared__ float  sh_dtsi[365];
    __shared__ float  sh_L[12];
    __shared__ float  sh_gE[12];
    __shared__ float2 sh_AB[12 * SLOTS];
    __shared__ float  sh_gT[12 * SLOTS];
    __shared__ float  sh_red[8];

    const int tid     = threadIdx.x;
    const int blockY0 = blockIdx.x * YPB;

    // ---- entry: generation stamp + scalars + own slot + (tid YPB-1) halo ----
    const float genExp = __ldcg(&g_gen) + 1.0f;     // read BEFORE any ticketing
    const float T1 = *pT1, T2 = *pT2, M1 = *pM1, M2 = *pM2;

    const int yy0 = blockY0 - W_YEARS + tid;        // own (warmup) year = slot tid
    const bool valid0 = (yy0 >= 0) && (yy0 < nyrs);
    float4 tq0 = make_float4(0.f,0.f,0.f,0.f), tq1 = tq0, tq2 = tq0;
    float4 pq0 = tq0, pq1 = tq0, pq2 = tq0;
    if (valid0) {
        const float4* Tv = reinterpret_cast<const float4*>(T + yy0 * 12);
        const float4* Pv = reinterpret_cast<const float4*>(P + yy0 * 12);
        tq0 = Tv[0]; tq1 = Tv[1]; tq2 = Tv[2];
        pq0 = Pv[0]; pq1 = Pv[1]; pq2 = Pv[2];
    }
    const int yyH = blockY0 + YPB - 1;              // halo year (slot YPB)
    const bool validH = (tid == YPB - 1) && (yyH < nyrs);   // warp 3, not warp 0
    float4 th0 = make_float4(0.f,0.f,0.f,0.f), th1 = th0, th2 = th0;
    float4 ph0 = th0, ph1 = th0, ph2 = th0;
    if (validH) {
        const float4* Tv = reinterpret_cast<const float4*>(T + yyH * 12);
        const float4* Pv = reinterpret_cast<const float4*>(P + yyH * 12);
        th0 = Tv[0]; th1 = Tv[1]; th2 = Tv[2];
        ph0 = Pv[0]; ph1 = Pv[1]; ph2 = Pv[2];
    }

    const float latr  = (float)(*phi_ptr) * (PI_F / 180.0f);
    const float invDT = 1.0f / (T2 - T1);
    const float invDM = 1.0f / (M2 - M1);

    // ---- stage 1: daily insolation (overlaps prefetch latency) ----
    const float tlat = __tanf(latr);
    const float slat = __sinf(latr);
    const float clat = __cosf(latr);
    for (int j = tid; j < 365; j += YPB) {
        float jday = (float)(j + 1);
        float ssd  = 0.39874907f * __sinf(PI_F * (jday - 80.0f) * (1.0f / 180.0f));
        float csd  = sqrtf(1.0f - ssd * ssd);
        float y    = fminf(fmaxf(-tlat * ssd * (1.0f / csd), -1.0f), 1.0f);
        float hdl  = fast_acos(y);
        float shdl = sqrtf(fmaxf(1.0f - y * y, 0.0f));
        sh_dtsi[j] = hdl * slat * ssd + clat * csd * shdl;
    }
    __syncthreads();

    // ---- warp 0: invmax -> gE, L (concurrent with phase A below) ----
    if (tid < 32) {
        float mx = -1.0f;
        for (int i = tid; i < 365; i += 32) mx = fmaxf(mx, sh_dtsi[i]);
        #pragma unroll
        for (int o = 16; o > 0; o >>= 1)
            mx = fmaxf(mx, __shfl_xor_sync(0xFFFFFFFF, mx, o));
        const float invmax = 1.0f / mx;
        if (tid < 12) {
            const int c0 = c_CDAYS[tid];
            const int c1 = c_CDAYS[tid + 1];
            float s = 0.0f;
            for (int i = c0; i < c1; i++) s += sh_dtsi[i];
            sh_gE[tid] = s * invmax / (float)(c1 - c0);

            float jday_mid = (float)c0 + 0.5f * c_NDAYS[tid + 1];
            float m_star = 1.0f - tlat * __tanf(0.40908772f * __cosf(jday_mid * (PI_F / 182.625f)));
            m_star = fminf(fmaxf(m_star, 0.0f), 2.0f);
            float nhrs = 24.0f * fast_acos(1.0f - m_star) * (1.0f / PI_F);
            sh_L[tid] = c_NDAYS[tid + 1] * (1.0f / 30.0f) * (nhrs * (1.0f / 12.0f));
        }
    }

    // ---- stage 2 phase A (no sh_L): I, a, invI in regs; gT,B' -> shared; B in regs ----
    float t[12] = { tq0.x,tq0.y,tq0.z,tq0.w, tq1.x,tq1.y,tq1.z,tq1.w, tq2.x,tq2.y,tq2.z,tq2.w };
    float Breg[12];
    float a_r = 0.0f, invI_r = 0.0f;
    if (valid0) {
        float p[12] = { pq0.x,pq0.y,pq0.z,pq0.w, pq1.x,pq1.y,pq1.z,pq1.w, pq2.x,pq2.y,pq2.z,pq2.w };
        float I = 0.0f;
        #pragma unroll
        for (int m = 0; m < 12; m++)
            I += fast_pow(fmaxf(t[m] * 0.2f, 0.0f), 1.514f);
        a_r    = ((6.75e-7f * I - 7.71e-5f) * I + 0.0179f) * I + 0.49f;
        invI_r = 1.0f / I;
        #pragma unroll
        for (int m = 0; m < 12; m++) {
            Breg[m] = p[m] * 1.31578947e-3f;                      // B' = p*0.001/0.76
            sh_AB[m*SLOTS + tid].y = Breg[m];
            sh_gT[m*SLOTS + tid]   = fminf(fmaxf((t[m] - T1) * invDT, 0.0f), 1.0f);
        }
    } else {
        #pragma unroll
        for (int m = 0; m < 12; m++) {
            Breg[m] = 0.0f;
            sh_AB[m*SLOTS + tid] = make_float2(1.0f, 0.0f);       // identity step
            sh_gT[m*SLOTS + tid] = 0.0f;
        }
    }
    // tid YPB-1: halo phase A (balances warp 0's gE work)
    float tH[12] = { th0.x,th0.y,th0.z,th0.w, th1.x,th1.y,th1.z,th1.w, th2.x,th2.y,th2.z,th2.w };
    float aH = 0.0f, invIH = 0.0f;
    if (tid == YPB - 1) {
        if (validH) {
            float pH[12] = { ph0.x,ph0.y,ph0.z,ph0.w, ph1.x,ph1.y,ph1.z,ph1.w, ph2.x,ph2.y,ph2.z,ph2.w };
            float I = 0.0f;
            #pragma unroll
            for (int m = 0; m < 12; m++)
                I += fast_pow(fmaxf(tH[m] * 0.2f, 0.0f), 1.514f);
            aH    = ((6.75e-7f * I - 7.71e-5f) * I + 0.0179f) * I + 0.49f;
            invIH = 1.0f / I;
            #pragma unroll
            for (int m = 0; m < 12; m++) {
                sh_AB[m*SLOTS + YPB].y = pH[m] * 1.31578947e-3f;
                sh_gT[m*SLOTS + YPB]   = fminf(fmaxf((tH[m] - T1) * invDT, 0.0f), 1.0f);
            }
        } else {
            #pragma unroll
            for (int m = 0; m < 12; m++) {
                sh_AB[m*SLOTS + YPB] = make_float2(1.0f, 0.0f);
                sh_gT[m*SLOTS + YPB] = 0.0f;
            }
        }
    }
    __syncthreads();     // sh_L + phase-A shared ready

    // ---- stage 2 phase B: A components (need sh_L); keep own A in regs ----
    float Areg[12];
    if (valid0) {
        #pragma unroll
        for (int m = 0; m < 12; m++) {
            float Tm = t[m];
            float ep = (Tm < 26.5f)
                ? 16.0f * sh_L[m] * fast_pow(fmaxf(10.0f * Tm * invI_r, 0.0f), a_r)
                : -415.85f + 32.25f * Tm - 0.43f * Tm * Tm;
            Areg[m] = 0.907f - ep * 1.31578947e-3f;
            sh_AB[m*SLOTS + tid].x = Areg[m];
        }
    } else {
        #pragma unroll
        for (int m = 0; m < 12; m++) Areg[m] = 1.0f;
    }
    if (validH) {
        #pragma unroll
        for (int m = 0; m < 12; m++) {
            float Tm = tH[m];
            float ep = (Tm < 26.5f)
                ? 16.0f * sh_L[m] * fast_pow(fmaxf(10.0f * Tm * invIH, 0.0f), aH)
                : -415.85f + 32.25f * Tm - 0.43f * Tm * Tm;
            sh_AB[m*SLOTS + YPB].x = 0.907f - ep * 1.31578947e-3f;
        }
    }

    // ---- stage 3a: warmup chain from OWN registers (before the barrier) ----
    const float PEXP = 4.886f;
    const float RMIN = 0.01f / 0.76f;
    float r = 0.2f / 0.76f;                 // M0 in r units
    #pragma unroll
    for (int m = 0; m < 12; m++) {
        float pw = fast_ex2(PEXP * fast_lg2(r));
        float tt = fmaf(Areg[m], r, Breg[m]);
        r = fminf(fmaxf(fmaf(-Breg[m], pw, tt), RMIN), 1.0f);
    }
    __syncthreads();     // neighbor/halo phase-B shared ready

    // ---- batch-prefetch real-year coefficients (slot tid+1) into registers ----
    float2 ABn[12];
    float  gTn[12];
    {
        const int s = tid + 1;
        #pragma unroll
        for (int m = 0; m < 12; m++) ABn[m] = sh_AB[m*SLOTS + s];
        #pragma unroll
        for (int m = 0; m < 12; m++) gTn[m] = sh_gT[m*SLOTS + s];
    }

    // ---- stage 3b: the real 12 months (pure registers + MUFU) ----
    const int y = blockY0 + tid;
    float w = 0.0f;
    if (y < nyrs) {
        const float c0g = 0.76f * invDM;
        const float c1g = -M1 * invDM;
        #pragma unroll
        for (int m = 0; m < 12; m++) {
            float pw = fast_ex2(PEXP * fast_lg2(r));
            float tt = fmaf(ABn[m].x, r, ABn[m].y);
            r = fminf(fmaxf(fmaf(-ABn[m].y, pw, tt), RMIN), 1.0f);

            float gM = fminf(fmaxf(fmaf(r, c0g, c1g), 0.0f), 1.0f);
            w = fmaf(fminf(gTn[m], gM), sh_gE[m], w);
        }
    }

    // ---- stage 4: block sums -> atomics; last arrival publishes {mean,inv,gen} ----
    {
        const int lane = tid & 31;
        const int wid  = tid >> 5;
        float s1 = w, s2 = w * w;
        #pragma unroll
        for (int o = 16; o > 0; o >>= 1) {
            s1 += __shfl_xor_sync(0xFFFFFFFF, s1, o);
            s2 += __shfl_xor_sync(0xFFFFFFFF, s2, o);
        }
        if (lane == 0) { sh_red[wid] = s1; sh_red[4 + wid] = s2; }
        __syncthreads();
        if (tid == 0) {
            float b1 = sh_red[0] + sh_red[1] + sh_red[2] + sh_red[3];
            float b2 = sh_red[4] + sh_red[5] + sh_red[6] + sh_red[7];
            atomicAdd(&g_sum, b1);
            atomicAdd(&g_sumsq, b2);
            __threadfence();
            unsigned int old = atomicAdd(&g_ticket, 1u);
            if (old == gridDim.x - 1u) {
                // every block fenced before its ticket add -> sums complete & visible
                const float n    = (float)nyrs;
                const float sum  = __ldcg(&g_sum);
                const float ssq  = __ldcg(&g_sumsq);
                const float mean = sum / n;
                const float inv  = rsqrtf((ssq - n * mean * mean) / (n - 1.0f));
                g_sum = 0.0f;                 // reset for next replay
                g_sumsq = 0.0f;
                g_ticket = 0;
                g_gen = genExp;
                asm volatile("st.global.cg.v4.f32 [%0], {%1, %2, %3, %4};"
                             :: "l"(&g_stats), "f"(mean), "f"(inv), "f"(genExp), "f"(0.0f)
                             : "memory");
            }
        }
    }

    // ---- stage 5: per-warp poll of the stats line, broadcast, store, exit ----
    {
        const int lane = tid & 31;
        float mean = 0.0f, inv = 0.0f;
        if (lane == 0) {
            float x0, x1, x2, x3;
            for (;;) {
                asm volatile("ld.global.cg.v4.f32 {%0, %1, %2, %3}, [%4];"
                             : "=f"(x0), "=f"(x1), "=f"(x2), "=f"(x3) : "l"(&g_stats));
                if (x2 == genExp) break;
                __nanosleep(20);
            }
            mean = x0; inv = x1;
        }
        mean = __shfl_sync(0xFFFFFFFF, mean, 0);
        inv  = __shfl_sync(0xFFFFFFFF, inv, 0);
        if (y < nyrs) out[y] = (w - mean) * inv;
    }
}

// ---------------- launch ----------------
extern "C" void kernel_launch(void* const* d_in, const int* in_sizes, int n_in,
                              void* d_out, int out_size) {
    const int*   phi = (const int*)d_in[2];
    const float* T   = (const float*)d_in[3];
    const float* P   = (const float*)d_in[4];
    const float* T1  = (const float*)d_in[5];
    const float* T2  = (const float*)d_in[6];
    const float* M1  = (const float*)d_in[7];
    const float* M2  = (const float*)d_in[8];
    float* out = (float*)d_out;

    const int nyrs = in_sizes[3] / 12;
    const int nblk = (nyrs + YPB - 1) / YPB;   // 64 <= 148 SMs: all co-resident

    vsl_fused_kernel<<<nblk, YPB>>>(phi, T, P, T1, T2, M1, M2, out, nyrs);
}